// round 3
// baseline (speedup 1.0000x reference)
#include <cuda_runtime.h>

#define NMAX 100000
#define EMAX 1600000
#define D 64

// ---- scratch (device globals; no runtime allocation) ----
__device__ float g_q[NMAX * D];
__device__ float g_k[NMAX * D];
__device__ float g_f[NMAX * D];
__device__ int   g_deg[NMAX];
__device__ int   g_off[NMAX];
__device__ int   g_cur[NMAX];
__device__ int   g_srcs[EMAX];

// ---------------------------------------------------------------------------
// CSR construction: zero counts -> count -> exclusive scan -> scatter
// ---------------------------------------------------------------------------
__global__ void zero_deg_kernel(int n) {
    int i = blockIdx.x * blockDim.x + threadIdx.x;
    if (i < n) g_deg[i] = 0;
}

__global__ void count_kernel(const int* __restrict__ dst, int e) {
    int i = blockIdx.x * blockDim.x + threadIdx.x;
    if (i < e) atomicAdd(&g_deg[dst[i]], 1);
}

// Single-block exclusive scan over g_deg -> g_off (also primes g_cur).
__global__ void scan_kernel(int n) {
    __shared__ int tmp[1024];
    int t = threadIdx.x;
    int chunk = (n + 1023) >> 10;
    int start = t * chunk;
    int end = min(start + chunk, n);
    int s = 0;
    for (int i = start; i < end; i++) s += g_deg[i];
    tmp[t] = s;
    __syncthreads();
    for (int off = 1; off < 1024; off <<= 1) {
        int v = (t >= off) ? tmp[t - off] : 0;
        __syncthreads();
        tmp[t] += v;
        __syncthreads();
    }
    int run = tmp[t] - s;  // exclusive prefix of this thread's chunk
    for (int i = start; i < end; i++) {
        int d = g_deg[i];
        g_off[i] = run;
        g_cur[i] = run;
        run += d;
    }
}

__global__ void scatter_kernel(const int* __restrict__ src,
                               const int* __restrict__ dst, int e) {
    int i = blockIdx.x * blockDim.x + threadIdx.x;
    if (i < e) {
        int p = atomicAdd(&g_cur[dst[i]], 1);
        g_srcs[p] = src[i];
    }
}

// ---------------------------------------------------------------------------
// Projection: out = feat @ W + b for W in {Wq, Wk, Wf} (blockIdx.y selects).
// 64 threads/block, 64-node x 64-col tile, 8x8 register micro-tile.
// ---------------------------------------------------------------------------
__global__ __launch_bounds__(64) void proj_kernel(
    const float* __restrict__ feat,
    const float* __restrict__ Wq, const float* __restrict__ bq,
    const float* __restrict__ Wk, const float* __restrict__ bk,
    const float* __restrict__ Wf, const float* __restrict__ bf,
    int n)
{
    __shared__ float fs[64][68];  // fs[k][node_local], padded, 16B-aligned rows
    __shared__ float ws[64][64];  // ws[k][col]  (same layout as W row-major)

    int which = blockIdx.y;
    const float* W    = (which == 0) ? Wq : (which == 1) ? Wk : Wf;
    const float* bias = (which == 0) ? bq : (which == 1) ? bk : bf;
    float* outp       = (which == 0) ? g_q : (which == 1) ? g_k : g_f;

    int node0 = blockIdx.x * 64;
    int t = threadIdx.x;

    // Load W (4096 floats) as float4
    #pragma unroll
    for (int i = 0; i < 16; i++)
        ((float4*)ws)[t + i * 64] = ((const float4*)W)[t + i * 64];

    // Load feat tile transposed: fs[k][m] = feat[node0+m][k]
    #pragma unroll 4
    for (int m = 0; m < 64; m++) {
        int row = node0 + m;
        if (row >= n) row = n - 1;  // clamp (stores are guarded)
        fs[t][m] = feat[row * 64 + t];
    }
    __syncthreads();

    int r = t >> 3, c = t & 7;
    float acc[8][8];
    #pragma unroll
    for (int i = 0; i < 8; i++)
        #pragma unroll
        for (int j = 0; j < 8; j++) acc[i][j] = 0.f;

    #pragma unroll 4
    for (int kk = 0; kk < 64; kk++) {
        float4 a0 = *(const float4*)&fs[kk][r * 8];
        float4 a1 = *(const float4*)&fs[kk][r * 8 + 4];
        float4 b0 = *(const float4*)&ws[kk][c * 8];
        float4 b1 = *(const float4*)&ws[kk][c * 8 + 4];
        float a[8] = {a0.x, a0.y, a0.z, a0.w, a1.x, a1.y, a1.z, a1.w};
        float b[8] = {b0.x, b0.y, b0.z, b0.w, b1.x, b1.y, b1.z, b1.w};
        #pragma unroll
        for (int i = 0; i < 8; i++)
            #pragma unroll
            for (int j = 0; j < 8; j++)
                acc[i][j] += a[i] * b[j];
    }

    float bb[8];
    #pragma unroll
    for (int j = 0; j < 8; j++) bb[j] = bias[c * 8 + j];

    #pragma unroll
    for (int i = 0; i < 8; i++) {
        int node = node0 + r * 8 + i;
        if (node < n) {
            float4 v0, v1;
            v0.x = acc[i][0] + bb[0]; v0.y = acc[i][1] + bb[1];
            v0.z = acc[i][2] + bb[2]; v0.w = acc[i][3] + bb[3];
            v1.x = acc[i][4] + bb[4]; v1.y = acc[i][5] + bb[5];
            v1.z = acc[i][6] + bb[6]; v1.w = acc[i][7] + bb[7];
            *(float4*)&outp[(size_t)node * 64 + c * 8]     = v0;
            *(float4*)&outp[(size_t)node * 64 + c * 8 + 4] = v1;
        }
    }
}

// ---------------------------------------------------------------------------
// Aggregation: one warp per destination node, online softmax over its edges.
// Per edge: e = leakyrelu(dot(k[src], q[dst])); running max/denominator;
// acc += exp(e-m) * f[src]; final out = acc / denom.
// ---------------------------------------------------------------------------
__global__ __launch_bounds__(256) void agg_kernel(float* __restrict__ out, int n) {
    int w = (int)((blockIdx.x * 256u + threadIdx.x) >> 5);
    int lane = threadIdx.x & 31;
    if (w >= n) return;

    int beg = g_off[w];
    int deg = g_deg[w];

    float2 qv = *(const float2*)&g_q[(size_t)w * 64 + lane * 2];

    float m = -1e30f;
    float s = 0.f;
    float ax = 0.f, ay = 0.f;

    for (int e = 0; e < deg; e++) {
        int sidx = g_srcs[beg + e];
        float2 kv = *(const float2*)&g_k[(size_t)sidx * 64 + lane * 2];
        float2 fv = *(const float2*)&g_f[(size_t)sidx * 64 + lane * 2];

        float d = kv.x * qv.x + kv.y * qv.y;
        #pragma unroll
        for (int o = 16; o; o >>= 1) d += __shfl_xor_sync(0xffffffffu, d, o);

        float el = d > 0.f ? d : 0.2f * d;  // leaky relu
        float mn = fmaxf(m, el);
        float sc  = __expf(m - mn);
        float wgt = __expf(el - mn);
        s  = s  * sc + wgt;
        ax = ax * sc + wgt * fv.x;
        ay = ay * sc + wgt * fv.y;
        m = mn;
    }

    float inv = (deg > 0) ? 1.f / s : 0.f;
    float2 o2;
    o2.x = ax * inv;
    o2.y = ay * inv;
    *(float2*)&out[(size_t)w * 64 + lane * 2] = o2;
}

// ---------------------------------------------------------------------------
// Launch
// ---------------------------------------------------------------------------
extern "C" void kernel_launch(void* const* d_in, const int* in_sizes, int n_in,
                              void* d_out, int out_size) {
    const float* feat = (const float*)d_in[0];
    const int*   src  = (const int*)d_in[1];
    const int*   dst  = (const int*)d_in[2];
    const float* Wq   = (const float*)d_in[3];
    const float* bq   = (const float*)d_in[4];
    const float* Wk   = (const float*)d_in[5];
    const float* bk   = (const float*)d_in[6];
    const float* Wf   = (const float*)d_in[7];
    const float* bf   = (const float*)d_in[8];
    float* out = (float*)d_out;

    int n = in_sizes[0] / D;   // nodes
    int e = in_sizes[1];       // edges

    // Projections (independent of CSR build)
    proj_kernel<<<dim3((n + 63) / 64, 3), 64>>>(feat, Wq, bq, Wk, bk, Wf, bf, n);

    // CSR build by dst
    zero_deg_kernel<<<(n + 255) / 256, 256>>>(n);
    count_kernel<<<(e + 255) / 256, 256>>>(dst, e);
    scan_kernel<<<1, 1024>>>(n);
    scatter_kernel<<<(e + 255) / 256, 256>>>(src, dst, e);

    // Warp-per-node online-softmax aggregation
    agg_kernel<<<(n + 7) / 8, 256>>>(out, n);
}

// round 4
// speedup vs baseline: 1.6861x; 1.6861x over previous
#include <cuda_runtime.h>

#define NMAX 100000
#define EMAX 1600000
#define D 64

// ---- scratch (device globals; no runtime allocation) ----
__device__ float g_q[NMAX * D];
__device__ float g_k[NMAX * D];
__device__ float g_f[NMAX * D];
__device__ int   g_deg[NMAX];
__device__ int   g_off[NMAX];
__device__ int   g_cur[NMAX];
__device__ int   g_srcs[EMAX];
__device__ int   g_tmp[NMAX];   // block-local exclusive scan values
__device__ int   g_bsum[256];   // per-block sums (<=98 blocks used)

// ---------------------------------------------------------------------------
// CSR construction: zero counts -> count -> 3-pass parallel scan -> scatter
// ---------------------------------------------------------------------------
__global__ void zero_deg_kernel(int n) {
    int i = blockIdx.x * blockDim.x + threadIdx.x;
    if (i < n) g_deg[i] = 0;
}

__global__ void count_kernel(const int* __restrict__ dst, int e) {
    int i = blockIdx.x * blockDim.x + threadIdx.x;
    if (i < e) atomicAdd(&g_deg[dst[i]], 1);
}

// Pass 1: per-block exclusive scan of g_deg (1024 elems/block) -> g_tmp,
// block total -> g_bsum[blockIdx].
__global__ __launch_bounds__(1024) void scan1_kernel(int n) {
    __shared__ int sh[1024];
    int t = threadIdx.x;
    int i = blockIdx.x * 1024 + t;
    int v = (i < n) ? g_deg[i] : 0;
    sh[t] = v;
    __syncthreads();
    #pragma unroll
    for (int off = 1; off < 1024; off <<= 1) {
        int x = (t >= off) ? sh[t - off] : 0;
        __syncthreads();
        sh[t] += x;
        __syncthreads();
    }
    if (i < n) g_tmp[i] = sh[t] - v;              // exclusive within block
    if (t == 1023) g_bsum[blockIdx.x] = sh[1023]; // block total
}

// Pass 2: single tiny block scans the block sums (nb <= 256).
__global__ __launch_bounds__(256) void scan2_kernel(int nb) {
    __shared__ int sh[256];
    int t = threadIdx.x;
    int v = (t < nb) ? g_bsum[t] : 0;
    sh[t] = v;
    __syncthreads();
    #pragma unroll
    for (int off = 1; off < 256; off <<= 1) {
        int x = (t >= off) ? sh[t - off] : 0;
        __syncthreads();
        sh[t] += x;
        __syncthreads();
    }
    if (t < nb) g_bsum[t] = sh[t] - v;            // exclusive block offsets
}

// Pass 3: combine -> g_off, g_cur.
__global__ void scan3_kernel(int n) {
    int i = blockIdx.x * blockDim.x + threadIdx.x;
    if (i < n) {
        int o = g_tmp[i] + g_bsum[i >> 10];
        g_off[i] = o;
        g_cur[i] = o;
    }
}

__global__ void scatter_kernel(const int* __restrict__ src,
                               const int* __restrict__ dst, int e) {
    int i = blockIdx.x * blockDim.x + threadIdx.x;
    if (i < e) {
        int p = atomicAdd(&g_cur[dst[i]], 1);
        g_srcs[p] = src[i];
    }
}

// ---------------------------------------------------------------------------
// Projection: out = feat @ W + b for W in {Wq, Wk, Wf} (blockIdx.y selects).
// 64 threads/block, 64-node x 64-col tile, 8x8 register micro-tile.
// ---------------------------------------------------------------------------
__global__ __launch_bounds__(64) void proj_kernel(
    const float* __restrict__ feat,
    const float* __restrict__ Wq, const float* __restrict__ bq,
    const float* __restrict__ Wk, const float* __restrict__ bk,
    const float* __restrict__ Wf, const float* __restrict__ bf,
    int n)
{
    __shared__ float fs[64][68];  // fs[k][node_local], padded
    __shared__ float ws[64][64];  // ws[k][col]

    int which = blockIdx.y;
    const float* W    = (which == 0) ? Wq : (which == 1) ? Wk : Wf;
    const float* bias = (which == 0) ? bq : (which == 1) ? bk : bf;
    float* outp       = (which == 0) ? g_q : (which == 1) ? g_k : g_f;

    int node0 = blockIdx.x * 64;
    int t = threadIdx.x;

    #pragma unroll
    for (int i = 0; i < 16; i++)
        ((float4*)ws)[t + i * 64] = ((const float4*)W)[t + i * 64];

    #pragma unroll 4
    for (int m = 0; m < 64; m++) {
        int row = node0 + m;
        if (row >= n) row = n - 1;  // clamp (stores are guarded)
        fs[t][m] = feat[row * 64 + t];
    }
    __syncthreads();

    int r = t >> 3, c = t & 7;
    float acc[8][8];
    #pragma unroll
    for (int i = 0; i < 8; i++)
        #pragma unroll
        for (int j = 0; j < 8; j++) acc[i][j] = 0.f;

    #pragma unroll 4
    for (int kk = 0; kk < 64; kk++) {
        float4 a0 = *(const float4*)&fs[kk][r * 8];
        float4 a1 = *(const float4*)&fs[kk][r * 8 + 4];
        float4 b0 = *(const float4*)&ws[kk][c * 8];
        float4 b1 = *(const float4*)&ws[kk][c * 8 + 4];
        float a[8] = {a0.x, a0.y, a0.z, a0.w, a1.x, a1.y, a1.z, a1.w};
        float b[8] = {b0.x, b0.y, b0.z, b0.w, b1.x, b1.y, b1.z, b1.w};
        #pragma unroll
        for (int i = 0; i < 8; i++)
            #pragma unroll
            for (int j = 0; j < 8; j++)
                acc[i][j] += a[i] * b[j];
    }

    float bb[8];
    #pragma unroll
    for (int j = 0; j < 8; j++) bb[j] = bias[c * 8 + j];

    #pragma unroll
    for (int i = 0; i < 8; i++) {
        int node = node0 + r * 8 + i;
        if (node < n) {
            float4 v0, v1;
            v0.x = acc[i][0] + bb[0]; v0.y = acc[i][1] + bb[1];
            v0.z = acc[i][2] + bb[2]; v0.w = acc[i][3] + bb[3];
            v1.x = acc[i][4] + bb[4]; v1.y = acc[i][5] + bb[5];
            v1.z = acc[i][6] + bb[6]; v1.w = acc[i][7] + bb[7];
            *(float4*)&outp[(size_t)node * 64 + c * 8]     = v0;
            *(float4*)&outp[(size_t)node * 64 + c * 8 + 4] = v1;
        }
    }
}

// ---------------------------------------------------------------------------
// Aggregation: one warp per destination node, online softmax over its edges.
// ---------------------------------------------------------------------------
__global__ __launch_bounds__(256) void agg_kernel(float* __restrict__ out, int n) {
    int w = (int)((blockIdx.x * 256u + threadIdx.x) >> 5);
    int lane = threadIdx.x & 31;
    if (w >= n) return;

    int beg = g_off[w];
    int deg = g_deg[w];

    float2 qv = *(const float2*)&g_q[(size_t)w * 64 + lane * 2];

    float m = -1e30f;
    float s = 0.f;
    float ax = 0.f, ay = 0.f;

    for (int e = 0; e < deg; e++) {
        int sidx = __ldg(&g_srcs[beg + e]);
        float2 kv = *(const float2*)&g_k[(size_t)sidx * 64 + lane * 2];
        float2 fv = *(const float2*)&g_f[(size_t)sidx * 64 + lane * 2];

        float d = kv.x * qv.x + kv.y * qv.y;
        #pragma unroll
        for (int o = 16; o; o >>= 1) d += __shfl_xor_sync(0xffffffffu, d, o);

        float el = d > 0.f ? d : 0.2f * d;  // leaky relu
        float mn = fmaxf(m, el);
        float sc  = __expf(m - mn);
        float wgt = __expf(el - mn);
        s  = s  * sc + wgt;
        ax = ax * sc + wgt * fv.x;
        ay = ay * sc + wgt * fv.y;
        m = mn;
    }

    float inv = (deg > 0) ? 1.f / s : 0.f;
    float2 o2;
    o2.x = ax * inv;
    o2.y = ay * inv;
    *(float2*)&out[(size_t)w * 64 + lane * 2] = o2;
}

// ---------------------------------------------------------------------------
// Launch
// ---------------------------------------------------------------------------
extern "C" void kernel_launch(void* const* d_in, const int* in_sizes, int n_in,
                              void* d_out, int out_size) {
    const float* feat = (const float*)d_in[0];
    const int*   src  = (const int*)d_in[1];
    const int*   dst  = (const int*)d_in[2];
    const float* Wq   = (const float*)d_in[3];
    const float* bq   = (const float*)d_in[4];
    const float* Wk   = (const float*)d_in[5];
    const float* bk   = (const float*)d_in[6];
    const float* Wf   = (const float*)d_in[7];
    const float* bf   = (const float*)d_in[8];
    float* out = (float*)d_out;

    int n = in_sizes[0] / D;   // nodes
    int e = in_sizes[1];       // edges
    int nb = (n + 1023) / 1024;

    // Projections (independent of CSR build)
    proj_kernel<<<dim3((n + 63) / 64, 3), 64>>>(feat, Wq, bq, Wk, bk, Wf, bf, n);

    // CSR build by dst (parallel two-level scan)
    zero_deg_kernel<<<(n + 255) / 256, 256>>>(n);
    count_kernel<<<(e + 255) / 256, 256>>>(dst, e);
    scan1_kernel<<<nb, 1024>>>(n);
    scan2_kernel<<<1, 256>>>(nb);
    scan3_kernel<<<(n + 255) / 256, 256>>>(n);
    scatter_kernel<<<(e + 255) / 256, 256>>>(src, dst, e);

    // Warp-per-node online-softmax aggregation
    agg_kernel<<<(n + 7) / 8, 256>>>(out, n);
}

// round 5
// speedup vs baseline: 1.7364x; 1.0298x over previous
#include <cuda_runtime.h>
#include <cstdint>

#define NMAX 100000
#define EMAX 1600000
#define D 64

// ---- scratch (device globals; no runtime allocation) ----
__device__ float g_q[NMAX * D];
__device__ float g_k[NMAX * D];
__device__ float g_f[NMAX * D];
__device__ int   g_deg[NMAX];
__device__ int   g_off[NMAX];
__device__ int   g_cur[NMAX];
__device__ int   g_srcs[EMAX];
__device__ int   g_tmp[NMAX];   // block-local exclusive scan values
__device__ int   g_bsum[256];   // per-block sums (<=98 blocks used)

// ---------------------------------------------------------------------------
// CSR construction: zero counts -> count -> 3-pass parallel scan -> scatter
// ---------------------------------------------------------------------------
__global__ void zero_deg_kernel(int n) {
    int i = blockIdx.x * blockDim.x + threadIdx.x;
    if (i < n) g_deg[i] = 0;
}

__global__ void count_kernel(const int* __restrict__ dst, int e) {
    int i = blockIdx.x * blockDim.x + threadIdx.x;
    if (i < e) atomicAdd(&g_deg[__ldg(&dst[i])], 1);  // result unused -> REDG
}

__global__ __launch_bounds__(1024) void scan1_kernel(int n) {
    __shared__ int sh[1024];
    int t = threadIdx.x;
    int i = blockIdx.x * 1024 + t;
    int v = (i < n) ? g_deg[i] : 0;
    sh[t] = v;
    __syncthreads();
    #pragma unroll
    for (int off = 1; off < 1024; off <<= 1) {
        int x = (t >= off) ? sh[t - off] : 0;
        __syncthreads();
        sh[t] += x;
        __syncthreads();
    }
    if (i < n) g_tmp[i] = sh[t] - v;              // exclusive within block
    if (t == 1023) g_bsum[blockIdx.x] = sh[1023]; // block total
}

__global__ __launch_bounds__(256) void scan2_kernel(int nb) {
    __shared__ int sh[256];
    int t = threadIdx.x;
    int v = (t < nb) ? g_bsum[t] : 0;
    sh[t] = v;
    __syncthreads();
    #pragma unroll
    for (int off = 1; off < 256; off <<= 1) {
        int x = (t >= off) ? sh[t - off] : 0;
        __syncthreads();
        sh[t] += x;
        __syncthreads();
    }
    if (t < nb) g_bsum[t] = sh[t] - v;            // exclusive block offsets
}

__global__ void scan3_kernel(int n) {
    int i = blockIdx.x * blockDim.x + threadIdx.x;
    if (i < n) {
        int o = g_tmp[i] + g_bsum[i >> 10];
        g_off[i] = o;
        g_cur[i] = o;
    }
}

__global__ void scatter_kernel(const int* __restrict__ src,
                               const int* __restrict__ dst, int e) {
    int i = blockIdx.x * blockDim.x + threadIdx.x;
    if (i < e) {
        int p = atomicAdd(&g_cur[__ldg(&dst[i])], 1);
        g_srcs[p] = __ldg(&src[i]);
    }
}

// ---------------------------------------------------------------------------
// Projection with packed f32x2 FMA (FFMA2). 64 threads, 64x64 tile,
// 8x8 micro-tile held as 4x8 packed 64-bit accumulators (pairs along M).
// ---------------------------------------------------------------------------
__global__ __launch_bounds__(64) void proj_kernel(
    const float* __restrict__ feat,
    const float* __restrict__ Wq, const float* __restrict__ bq,
    const float* __restrict__ Wk, const float* __restrict__ bk,
    const float* __restrict__ Wf, const float* __restrict__ bf,
    int n)
{
    __shared__ float fs[64][68];  // fs[k][node_local], padded
    __shared__ float ws[64][64];  // ws[k][col]

    int which = blockIdx.y;
    const float* W    = (which == 0) ? Wq : (which == 1) ? Wk : Wf;
    const float* bias = (which == 0) ? bq : (which == 1) ? bk : bf;
    float* outp       = (which == 0) ? g_q : (which == 1) ? g_k : g_f;

    int node0 = blockIdx.x * 64;
    int t = threadIdx.x;

    #pragma unroll
    for (int i = 0; i < 16; i++)
        ((float4*)ws)[t + i * 64] = ((const float4*)W)[t + i * 64];

    #pragma unroll 4
    for (int m = 0; m < 64; m++) {
        int row = node0 + m;
        if (row >= n) row = n - 1;  // clamp (stores are guarded)
        fs[t][m] = feat[row * 64 + t];
    }
    __syncthreads();

    int r = t >> 3, c = t & 7;

    // acc[i2][j] packs output rows (r*8+2*i2, r*8+2*i2+1), column c*8+j
    unsigned long long acc[4][8];
    #pragma unroll
    for (int i = 0; i < 4; i++)
        #pragma unroll
        for (int j = 0; j < 8; j++) acc[i][j] = 0ull;

    const float* fsr = &fs[0][r * 8];

    #pragma unroll 2
    for (int kk = 0; kk < 64; kk++) {
        // 4 packed A pairs (contiguous along m in fs row kk)
        unsigned long long a2[4];
        #pragma unroll
        for (int i = 0; i < 4; i++)
            a2[i] = *(const unsigned long long*)(fsr + kk * 68 + 2 * i);

        #pragma unroll
        for (int j = 0; j < 8; j++) {
            unsigned int bb = __float_as_uint(ws[kk][c * 8 + j]);
            unsigned long long b2;
            asm("mov.b64 %0, {%1, %1};" : "=l"(b2) : "r"(bb));
            #pragma unroll
            for (int i = 0; i < 4; i++)
                asm("fma.rn.f32x2 %0, %1, %2, %0;"
                    : "+l"(acc[i][j]) : "l"(a2[i]), "l"(b2));
        }
    }

    float bbv[8];
    #pragma unroll
    for (int j = 0; j < 8; j++) bbv[j] = bias[c * 8 + j];

    #pragma unroll
    for (int i2 = 0; i2 < 4; i2++) {
        float lo[8], hi[8];
        #pragma unroll
        for (int j = 0; j < 8; j++) {
            unsigned int ulo, uhi;
            asm("mov.b64 {%0, %1}, %2;" : "=r"(ulo), "=r"(uhi) : "l"(acc[i2][j]));
            lo[j] = __uint_as_float(ulo) + bbv[j];
            hi[j] = __uint_as_float(uhi) + bbv[j];
        }
        int node = node0 + r * 8 + 2 * i2;
        if (node < n) {
            *(float4*)&outp[(size_t)node * 64 + c * 8]     = make_float4(lo[0], lo[1], lo[2], lo[3]);
            *(float4*)&outp[(size_t)node * 64 + c * 8 + 4] = make_float4(lo[4], lo[5], lo[6], lo[7]);
        }
        if (node + 1 < n) {
            *(float4*)&outp[(size_t)(node + 1) * 64 + c * 8]     = make_float4(hi[0], hi[1], hi[2], hi[3]);
            *(float4*)&outp[(size_t)(node + 1) * 64 + c * 8 + 4] = make_float4(hi[4], hi[5], hi[6], hi[7]);
        }
    }
}

// ---------------------------------------------------------------------------
// Aggregation: one warp per destination node, online softmax over its edges.
// Batched index loads (32 at a time) + warp-uniform rescale branch.
// ---------------------------------------------------------------------------
__global__ __launch_bounds__(256) void agg_kernel(float* __restrict__ out, int n) {
    int w = (int)((blockIdx.x * 256u + threadIdx.x) >> 5);
    int lane = threadIdx.x & 31;
    if (w >= n) return;

    int beg = g_off[w];
    int deg = g_deg[w];

    float2 qv = *(const float2*)&g_q[(size_t)w * 64 + lane * 2];

    float m = -1e30f;
    float s = 0.f;
    float ax = 0.f, ay = 0.f;

    for (int base = 0; base < deg; base += 32) {
        int cnt = min(32, deg - base);
        int myidx = (lane < cnt) ? __ldg(&g_srcs[beg + base + lane]) : 0;

        for (int j = 0; j < cnt; j++) {
            int sidx = __shfl_sync(0xffffffffu, myidx, j);
            float2 kv = *(const float2*)&g_k[(size_t)sidx * 64 + lane * 2];
            float2 fv = *(const float2*)&g_f[(size_t)sidx * 64 + lane * 2];

            float d = kv.x * qv.x + kv.y * qv.y;
            #pragma unroll
            for (int o = 16; o; o >>= 1) d += __shfl_xor_sync(0xffffffffu, d, o);

            float el = d > 0.f ? d : 0.2f * d;  // leaky relu (warp-uniform)

            if (el > m) {
                // new max: rescale previous state (uniform branch, rare)
                float sc = __expf(m - el);   // expf(-inf)=0 on first edge
                s  = s  * sc + 1.f;
                ax = ax * sc + fv.x;
                ay = ay * sc + fv.y;
                m = el;
            } else {
                float wgt = __expf(el - m);
                s  += wgt;
                ax += wgt * fv.x;
                ay += wgt * fv.y;
            }
        }
    }

    float inv = (deg > 0) ? 1.f / s : 0.f;
    float2 o2;
    o2.x = ax * inv;
    o2.y = ay * inv;
    *(float2*)&out[(size_t)w * 64 + lane * 2] = o2;
}

// ---------------------------------------------------------------------------
// Launch
// ---------------------------------------------------------------------------
extern "C" void kernel_launch(void* const* d_in, const int* in_sizes, int n_in,
                              void* d_out, int out_size) {
    const float* feat = (const float*)d_in[0];
    const int*   src  = (const int*)d_in[1];
    const int*   dst  = (const int*)d_in[2];
    const float* Wq   = (const float*)d_in[3];
    const float* bq   = (const float*)d_in[4];
    const float* Wk   = (const float*)d_in[5];
    const float* bk   = (const float*)d_in[6];
    const float* Wf   = (const float*)d_in[7];
    const float* bf   = (const float*)d_in[8];
    float* out = (float*)d_out;

    int n = in_sizes[0] / D;   // nodes
    int e = in_sizes[1];       // edges
    int nb = (n + 1023) / 1024;

    // Projections (independent of CSR build)
    proj_kernel<<<dim3((n + 63) / 64, 3), 64>>>(feat, Wq, bq, Wk, bk, Wf, bf, n);

    // CSR build by dst (parallel two-level scan)
    zero_deg_kernel<<<(n + 255) / 256, 256>>>(n);
    count_kernel<<<(e + 255) / 256, 256>>>(dst, e);
    scan1_kernel<<<nb, 1024>>>(n);
    scan2_kernel<<<1, 256>>>(nb);
    scan3_kernel<<<(n + 255) / 256, 256>>>(n);
    scatter_kernel<<<(e + 255) / 256, 256>>>(src, dst, e);

    // Warp-per-node online-softmax aggregation
    agg_kernel<<<(n + 7) / 8, 256>>>(out, n);
}

// round 6
// speedup vs baseline: 1.7706x; 1.0197x over previous
#include <cuda_runtime.h>
#include <cstdint>

#define NMAX 100000
#define EMAX 1600000
#define D 64

// ---- scratch (device globals; no runtime allocation) ----
__device__ float g_q[NMAX * D];
__device__ float g_kf[NMAX * 2 * D];   // interleaved: [node][(col/2)*4 + {k0,k1,f0,f1}]
__device__ int   g_deg[NMAX];
__device__ int   g_off[NMAX];
__device__ int   g_cur[NMAX];
__device__ int   g_srcs[EMAX];
__device__ int   g_tmp[NMAX];
__device__ int   g_bsum[256];

// ---------------------------------------------------------------------------
// CSR construction: zero counts -> count -> 3-pass parallel scan -> scatter
// ---------------------------------------------------------------------------
__global__ void zero_deg_kernel(int n) {
    int i = blockIdx.x * blockDim.x + threadIdx.x;
    if (i < n) g_deg[i] = 0;
}

__global__ void count_kernel(const int* __restrict__ dst, int e) {
    int i = blockIdx.x * blockDim.x + threadIdx.x;
    if (i < e) atomicAdd(&g_deg[__ldg(&dst[i])], 1);
}

__global__ __launch_bounds__(1024) void scan1_kernel(int n) {
    __shared__ int sh[1024];
    int t = threadIdx.x;
    int i = blockIdx.x * 1024 + t;
    int v = (i < n) ? g_deg[i] : 0;
    sh[t] = v;
    __syncthreads();
    #pragma unroll
    for (int off = 1; off < 1024; off <<= 1) {
        int x = (t >= off) ? sh[t - off] : 0;
        __syncthreads();
        sh[t] += x;
        __syncthreads();
    }
    if (i < n) g_tmp[i] = sh[t] - v;
    if (t == 1023) g_bsum[blockIdx.x] = sh[1023];
}

__global__ __launch_bounds__(256) void scan2_kernel(int nb) {
    __shared__ int sh[256];
    int t = threadIdx.x;
    int v = (t < nb) ? g_bsum[t] : 0;
    sh[t] = v;
    __syncthreads();
    #pragma unroll
    for (int off = 1; off < 256; off <<= 1) {
        int x = (t >= off) ? sh[t - off] : 0;
        __syncthreads();
        sh[t] += x;
        __syncthreads();
    }
    if (t < nb) g_bsum[t] = sh[t] - v;
}

__global__ void scan3_kernel(int n) {
    int i = blockIdx.x * blockDim.x + threadIdx.x;
    if (i < n) {
        int o = g_tmp[i] + g_bsum[i >> 10];
        g_off[i] = o;
        g_cur[i] = o;
    }
}

__global__ void scatter_kernel(const int* __restrict__ src,
                               const int* __restrict__ dst, int e) {
    int i = blockIdx.x * blockDim.x + threadIdx.x;
    if (i < e) {
        int p = atomicAdd(&g_cur[__ldg(&dst[i])], 1);
        g_srcs[p] = __ldg(&src[i]);
    }
}

// ---------------------------------------------------------------------------
// Fused projection: feat tile loaded ONCE, then q/k/f weight passes run
// sequentially. k and f are written interleaved into g_kf.
// 64 threads, 64x64 tile, packed-f32x2 FMA micro-tile.
// ---------------------------------------------------------------------------
__global__ __launch_bounds__(64) void proj_kernel(
    const float* __restrict__ feat,
    const float* __restrict__ Wq, const float* __restrict__ bq,
    const float* __restrict__ Wk, const float* __restrict__ bk,
    const float* __restrict__ Wf, const float* __restrict__ bf,
    int n)
{
    __shared__ float fs[64][68];  // fs[k][node_local], padded
    __shared__ float ws[64][64];  // ws[k][col]

    int node0 = blockIdx.x * 64;
    int t = threadIdx.x;

    // Load feat tile transposed: fs[k][m] = feat[node0+m][k]  (once)
    #pragma unroll 4
    for (int m = 0; m < 64; m++) {
        int row = node0 + m;
        if (row >= n) row = n - 1;  // clamp (stores are guarded)
        fs[t][m] = feat[row * 64 + t];
    }

    int r = t >> 3, c = t & 7;
    const float* fsr = &fs[0][r * 8];

    #pragma unroll
    for (int which = 0; which < 3; which++) {
        const float* W    = (which == 0) ? Wq : (which == 1) ? Wk : Wf;
        const float* bias = (which == 0) ? bq : (which == 1) ? bk : bf;

        __syncthreads();   // fs ready (pass 0) / prior pass done reading ws
        #pragma unroll
        for (int i = 0; i < 16; i++)
            ((float4*)ws)[t + i * 64] = ((const float4*)W)[t + i * 64];
        __syncthreads();

        // acc[i2][j]: packed output rows (r*8+2*i2, +1), column c*8+j
        unsigned long long acc[4][8];
        #pragma unroll
        for (int i = 0; i < 4; i++)
            #pragma unroll
            for (int j = 0; j < 8; j++) acc[i][j] = 0ull;

        #pragma unroll 2
        for (int kk = 0; kk < 64; kk++) {
            unsigned long long a2[4];
            #pragma unroll
            for (int i = 0; i < 4; i++)
                a2[i] = *(const unsigned long long*)(fsr + kk * 68 + 2 * i);

            #pragma unroll
            for (int j = 0; j < 8; j++) {
                unsigned int bb = __float_as_uint(ws[kk][c * 8 + j]);
                unsigned long long b2;
                asm("mov.b64 %0, {%1, %1};" : "=l"(b2) : "r"(bb));
                #pragma unroll
                for (int i = 0; i < 4; i++)
                    asm("fma.rn.f32x2 %0, %1, %2, %0;"
                        : "+l"(acc[i][j]) : "l"(a2[i]), "l"(b2));
            }
        }

        float bbv[8];
        #pragma unroll
        for (int j = 0; j < 8; j++) bbv[j] = bias[c * 8 + j];

        #pragma unroll
        for (int i2 = 0; i2 < 4; i2++) {
            float lo[8], hi[8];
            #pragma unroll
            for (int j = 0; j < 8; j++) {
                unsigned int ulo, uhi;
                asm("mov.b64 {%0, %1}, %2;" : "=r"(ulo), "=r"(uhi) : "l"(acc[i2][j]));
                lo[j] = __uint_as_float(ulo) + bbv[j];
                hi[j] = __uint_as_float(uhi) + bbv[j];
            }
            int node = node0 + r * 8 + 2 * i2;
            if (which == 0) {
                if (node < n) {
                    *(float4*)&g_q[(size_t)node * 64 + c * 8]     = make_float4(lo[0], lo[1], lo[2], lo[3]);
                    *(float4*)&g_q[(size_t)node * 64 + c * 8 + 4] = make_float4(lo[4], lo[5], lo[6], lo[7]);
                }
                if (node + 1 < n) {
                    *(float4*)&g_q[(size_t)(node + 1) * 64 + c * 8]     = make_float4(hi[0], hi[1], hi[2], hi[3]);
                    *(float4*)&g_q[(size_t)(node + 1) * 64 + c * 8 + 4] = make_float4(hi[4], hi[5], hi[6], hi[7]);
                }
            } else {
                // interleaved kf: col (8c+2i, 8c+2i+1) -> kf[node*128 + (4c+i)*4 + add]
                int add = (which == 1) ? 0 : 2;
                if (node < n) {
                    #pragma unroll
                    for (int i = 0; i < 4; i++)
                        *(float2*)&g_kf[(size_t)node * 128 + (4 * c + i) * 4 + add] =
                            make_float2(lo[2 * i], lo[2 * i + 1]);
                }
                if (node + 1 < n) {
                    #pragma unroll
                    for (int i = 0; i < 4; i++)
                        *(float2*)&g_kf[(size_t)(node + 1) * 128 + (4 * c + i) * 4 + add] =
                            make_float2(hi[2 * i], hi[2 * i + 1]);
                }
            }
        }
    }
}

// ---------------------------------------------------------------------------
// Aggregation: one warp per destination node; edges processed in pairs for
// ILP; single LDG.128 per lane fetches k-pair AND f-pair (interleaved kf).
// ---------------------------------------------------------------------------
__global__ __launch_bounds__(256) void agg_kernel(float* __restrict__ out, int n) {
    int w = (int)((blockIdx.x * 256u + threadIdx.x) >> 5);
    int lane = threadIdx.x & 31;
    if (w >= n) return;

    int beg = g_off[w];
    int deg = g_deg[w];

    float2 qv = *(const float2*)&g_q[(size_t)w * 64 + lane * 2];
    float qx = qv.x, qy = qv.y;

    float m = -1e30f;
    float s = 0.f;
    float ax = 0.f, ay = 0.f;

    for (int base = 0; base < deg; base += 32) {
        int cnt = min(32, deg - base);
        int myidx = (lane < cnt) ? __ldg(&g_srcs[beg + base + lane]) : 0;

        int j = 0;
        for (; j + 1 < cnt; j += 2) {
            int s0 = __shfl_sync(0xffffffffu, myidx, j);
            int s1 = __shfl_sync(0xffffffffu, myidx, j + 1);
            float4 a = __ldg((const float4*)&g_kf[(size_t)s0 * 128 + lane * 4]);
            float4 b = __ldg((const float4*)&g_kf[(size_t)s1 * 128 + lane * 4]);

            float d0 = a.x * qx + a.y * qy;
            float d1 = b.x * qx + b.y * qy;
            #pragma unroll
            for (int o = 16; o; o >>= 1) {
                d0 += __shfl_xor_sync(0xffffffffu, d0, o);
                d1 += __shfl_xor_sync(0xffffffffu, d1, o);
            }

            float e0 = d0 > 0.f ? d0 : 0.2f * d0;
            float e1 = d1 > 0.f ? d1 : 0.2f * d1;

            float mb = fmaxf(e0, e1);
            float mn = fmaxf(m, mb);
            float sc = __expf(m - mn);     // 0 on first pair (m=-1e30)
            float w0 = __expf(e0 - mn);
            float w1 = __expf(e1 - mn);
            s  = s  * sc + w0 + w1;
            ax = ax * sc + w0 * a.z + w1 * b.z;
            ay = ay * sc + w0 * a.w + w1 * b.w;
            m = mn;
        }
        if (j < cnt) {  // odd tail
            int s0 = __shfl_sync(0xffffffffu, myidx, j);
            float4 a = __ldg((const float4*)&g_kf[(size_t)s0 * 128 + lane * 4]);
            float d0 = a.x * qx + a.y * qy;
            #pragma unroll
            for (int o = 16; o; o >>= 1) d0 += __shfl_xor_sync(0xffffffffu, d0, o);
            float e0 = d0 > 0.f ? d0 : 0.2f * d0;
            float mn = fmaxf(m, e0);
            float sc = __expf(m - mn);
            float w0 = __expf(e0 - mn);
            s  = s  * sc + w0;
            ax = ax * sc + w0 * a.z;
            ay = ay * sc + w0 * a.w;
            m = mn;
        }
    }

    float inv = (deg > 0) ? 1.f / s : 0.f;
    float2 o2;
    o2.x = ax * inv;
    o2.y = ay * inv;
    *(float2*)&out[(size_t)w * 64 + lane * 2] = o2;
}

// ---------------------------------------------------------------------------
// Launch
// ---------------------------------------------------------------------------
extern "C" void kernel_launch(void* const* d_in, const int* in_sizes, int n_in,
                              void* d_out, int out_size) {
    const float* feat = (const float*)d_in[0];
    const int*   src  = (const int*)d_in[1];
    const int*   dst  = (const int*)d_in[2];
    const float* Wq   = (const float*)d_in[3];
    const float* bq   = (const float*)d_in[4];
    const float* Wk   = (const float*)d_in[5];
    const float* bk   = (const float*)d_in[6];
    const float* Wf   = (const float*)d_in[7];
    const float* bf   = (const float*)d_in[8];
    float* out = (float*)d_out;

    int n = in_sizes[0] / D;   // nodes
    int e = in_sizes[1];       // edges
    int nb = (n + 1023) / 1024;

    // Fused projections (independent of CSR build)
    proj_kernel<<<(n + 63) / 64, 64>>>(feat, Wq, bq, Wk, bk, Wf, bf, n);

    // CSR build by dst (parallel two-level scan)
    zero_deg_kernel<<<(n + 255) / 256, 256>>>(n);
    count_kernel<<<(e + 255) / 256, 256>>>(dst, e);
    scan1_kernel<<<nb, 1024>>>(n);
    scan2_kernel<<<1, 256>>>(nb);
    scan3_kernel<<<(n + 255) / 256, 256>>>(n);
    scatter_kernel<<<(e + 255) / 256, 256>>>(src, dst, e);

    // Warp-per-node online-softmax aggregation
    agg_kernel<<<(n + 7) / 8, 256>>>(out, n);
}